// round 17
// baseline (speedup 1.0000x reference)
#include <cuda_runtime.h>
#include <cuda_fp16.h>
#include <cstdint>

#define N_CELLS 10000
#define N_GENES 2000
#define DD      64
#define TILE    128
#define MT      79                  // ceil(10000/128)
#define NTT     47                  // 6016/128
#define MG      8                   // mtiles per CTA
#define NGRP    10                  // ceil(79/8)
#define M_PAD   (MT * TILE)         // 10112
#define N_COLS  (3 * N_GENES)       // 6000  (n = gene*3 + head)
#define N_PAD   (NTT * TILE)        // 6016
#define SA      144                 // smem row stride bytes

// ---------------- device scratch (static; no runtime allocation) ------------
__device__ __half g_Ah[M_PAD * DD];
__device__ __half g_Bh[N_PAD * DD];
__device__ __half g_Ch[(size_t)M_PAD * N_PAD];   // 121.6 MB

// ---------------- helpers ----------------------------------------------------
__device__ __forceinline__ uint32_t smem_u32(const void* p) {
    uint32_t a;
    asm("{ .reg .u64 t; cvta.to.shared.u64 t, %1; cvt.u32.u64 %0, t; }" : "=r"(a) : "l"(p));
    return a;
}

__device__ __forceinline__ void ldm4(uint32_t* r, uint32_t addr) {
    asm volatile("ldmatrix.sync.aligned.m8n8.x4.shared.b16 {%0,%1,%2,%3}, [%4];"
                 : "=r"(r[0]), "=r"(r[1]), "=r"(r[2]), "=r"(r[3]) : "r"(addr));
}

__device__ __forceinline__ void mma16816(float* c, const uint32_t* a,
                                         uint32_t b0, uint32_t b1) {
    asm volatile(
        "mma.sync.aligned.m16n8k16.row.col.f32.f16.f16.f32 "
        "{%0,%1,%2,%3}, {%4,%5,%6,%7}, {%8,%9}, {%0,%1,%2,%3};"
        : "+f"(c[0]), "+f"(c[1]), "+f"(c[2]), "+f"(c[3])
        : "r"(a[0]), "r"(a[1]), "r"(a[2]), "r"(a[3]), "r"(b0), "r"(b1));
}

__device__ __forceinline__ uint64_t mk_pol_evict_last() {
    uint64_t p;
    asm("createpolicy.fractional.L2::evict_last.b64 %0, 1.0;" : "=l"(p));
    return p;
}

__device__ __forceinline__ void st_c_el(__half* p, __half2 v, uint64_t pol) {
    asm volatile("st.global.L2::cache_hint.u32 [%0], %1, %2;"
                 :: "l"(p), "r"(*(uint32_t*)&v), "l"(pol) : "memory");
}

__device__ __forceinline__ uint32_t ld_c32_el(const uint32_t* p, uint64_t pol) {
    uint32_t v;
    asm volatile("ld.global.nc.L2::cache_hint.u32 %0, [%1], %2;"
                 : "=r"(v) : "l"(p), "l"(pol));
    return v;
}

// ---------------- phase 0: prep (A fp16; B fp16) -----------------------------
__global__ void prep_AB(const float* __restrict__ c_feat,
                        const float* __restrict__ g_feat,
                        const float* __restrict__ Wm,
                        const float* __restrict__ Wd,
                        const float* __restrict__ Wp) {
    int i = blockIdx.x * blockDim.x + threadIdx.x;
    const int NA = M_PAD * DD;
    if (i < NA) {
        int m = i >> 6;
        float v = (m < N_CELLS) ? c_feat[i] : 0.0f;
        g_Ah[i] = __float2half_rn(v);
    } else {
        int j = i - NA;
        if (j >= N_PAD * DD) return;
        int n = j >> 6;
        int k = j & 63;
        float v = 0.0f;
        if (n < N_COLS) {
            int gene = n / 3;
            int head = n - gene * 3;
            const float* W = (head == 0) ? Wm : (head == 1 ? Wd : Wp);
            v = g_feat[gene * DD + k] * W[k];
        }
        g_Bh[j] = __float2half_rn(v);
    }
}

// ---------------- phase 1: HMMA GEMM  C = A @ B^T  (single fp16 pass) --------
// Grid (NTT, NGRP). Each CTA: B tile resident (smem + reg fragments),
// loops MG mtiles with double-buffered A. Warp tile 32(m) x 64(n).
__global__ __launch_bounds__(256) void zinb_gemm() {
    extern __shared__ __align__(16) char sm[];
    const int OB = 0, OA0 = 18432, OA1 = 36864;   // 128*144 each

    const int tid   = threadIdx.x;
    const int ntile = blockIdx.x;
    const int mgrp  = blockIdx.y;
    const int m0    = mgrp * MG;

    // Cooperative load: B tile + first A tile.
    {
        const uint4* B4 = (const uint4*)g_Bh + (size_t)ntile * 1024;
        const uint4* A4 = (const uint4*)g_Ah + (size_t)m0 * 1024;
        #pragma unroll
        for (int it = 0; it < 4; it++) {
            int idx = tid + it * 256;       // 0..1023
            int row = idx >> 3, c = idx & 7;
            int off = row * SA + c * 16;
            *(uint4*)(sm + OB + off) = B4[idx];
            *(uint4*)(sm + OA0 + off) = A4[idx];
        }
    }
    __syncthreads();

    const uint32_t sbase = smem_u32(sm);
    const int wid = tid >> 5, lane = tid & 31;
    const int wm = wid & 3, wn = wid >> 2;
    const int lr = lane & 15, lc = lane >> 4;

    // Hoist B fragments into registers (loop-invariant across mtiles).
    uint32_t bfrag[4][4][4];   // [k][np][reg]
    #pragma unroll
    for (int k = 0; k < 4; k++)
        #pragma unroll
        for (int np = 0; np < 4; np++)
            ldm4(bfrag[k][np],
                 sbase + OB + (wn * 64 + np * 16 + lr) * SA + k * 32 + lc * 16);

    const uint64_t pol = mk_pol_evict_last();

    for (int mi = 0; mi < MG; mi++) {
        const int mtile = m0 + mi;
        if (mtile >= MT) break;

        // Prefetch next A tile into the other buffer (no readers there).
        const int nmt = mtile + 1;
        if (mi + 1 < MG && nmt < MT) {
            const uint4* A4 = (const uint4*)g_Ah + (size_t)nmt * 1024;
            char* dst = sm + ((mi & 1) ? OA0 : OA1);
            #pragma unroll
            for (int it = 0; it < 4; it++) {
                int idx = tid + it * 256;
                int row = idx >> 3, c = idx & 7;
                *(uint4*)(dst + row * SA + c * 16) = A4[idx];
            }
        }

        const uint32_t abase = sbase + ((mi & 1) ? OA1 : OA0);

        float acc[2][8][4];
        #pragma unroll
        for (int i = 0; i < 2; i++)
            #pragma unroll
            for (int j = 0; j < 8; j++)
                #pragma unroll
                for (int q = 0; q < 4; q++) acc[i][j][q] = 0.0f;

        #pragma unroll
        for (int k = 0; k < 4; k++) {
            uint32_t a[2][4];
            #pragma unroll
            for (int mt = 0; mt < 2; mt++)
                ldm4(a[mt], abase + (wm * 32 + mt * 16 + lr) * SA + k * 32 + lc * 16);
            #pragma unroll
            for (int mt = 0; mt < 2; mt++)
                #pragma unroll
                for (int nt = 0; nt < 8; nt++)
                    mma16816(acc[mt][nt], a[mt],
                             bfrag[k][nt >> 1][nt & 1], bfrag[k][nt >> 1][(nt & 1) + 2]);
        }

        // Store C tile (fp16, evict_last).
        #pragma unroll
        for (int mt = 0; mt < 2; mt++) {
            const int r0 = mtile * TILE + wm * 32 + mt * 16 + (lane >> 2);
            #pragma unroll
            for (int nt = 0; nt < 8; nt++) {
                const int c0 = ntile * TILE + wn * 64 + nt * 8 + (lane & 3) * 2;
                st_c_el(&g_Ch[(size_t)r0 * N_PAD + c0],
                        __floats2half2_rn(acc[mt][nt][0], acc[mt][nt][1]), pol);
                st_c_el(&g_Ch[(size_t)(r0 + 8) * N_PAD + c0],
                        __floats2half2_rn(acc[mt][nt][2], acc[mt][nt][3]), pol);
            }
        }
        __syncthreads();
    }
}

// ---------------- phase 2: per-edge gather + activations ---------------------
// Persistent grid-stride; cs/gs factors in shared memory (divergent factor
// reads become ~4-cycle LDS instead of ~27 L1tex wavefronts); 2 edges per
// thread via split halves; two aligned u32 loads cover each fp16 triple.
__global__ __launch_bounds__(256) void zinb_gather(
    const int* __restrict__ src, const int* __restrict__ dst,
    const float* __restrict__ cs_factor, const float* __restrict__ gs_factor,
    const float* __restrict__ bm, const float* __restrict__ bd,
    const float* __restrict__ bp,
    float* __restrict__ out, int E)
{
    __shared__ float s_cs[N_CELLS];   // 40000 B
    __shared__ float s_gs[N_GENES];   //  8000 B
    {
        const float4* c4 = (const float4*)cs_factor;
        const float4* g4 = (const float4*)gs_factor;
        for (int i = threadIdx.x; i < N_CELLS / 4; i += blockDim.x)
            *(float4*)&s_cs[i * 4] = c4[i];
        for (int i = threadIdx.x; i < N_GENES / 4; i += blockDim.x)
            *(float4*)&s_gs[i * 4] = g4[i];
    }
    __syncthreads();

    const float bmv = __ldg(bm), bdv = __ldg(bd), bpv = __ldg(bp);
    const uint64_t pol = mk_pol_evict_last();
    const uint32_t* cw = (const uint32_t*)g_Ch;

    const int half = (E + 1) >> 1;
    const int stride = gridDim.x * blockDim.x;

    for (int t = blockIdx.x * blockDim.x + threadIdx.x; t < half; t += stride) {
        const int e0 = t;
        const int e1 = t + half;
        const bool v1 = (e1 < E);

        const int s0 = __ldcs(src + e0);
        const int d0 = __ldcs(dst + e0);
        const int s1 = v1 ? __ldcs(src + e1) : 0;
        const int d1 = v1 ? __ldcs(dst + e1) : 0;

        const size_t h0 = (size_t)s0 * N_PAD + 3 * (size_t)d0;
        const size_t h1 = (size_t)s1 * N_PAD + 3 * (size_t)d1;
        const size_t w0 = h0 >> 1, w1 = h1 >> 1;
        const bool o0 = (h0 & 1), o1 = (h1 & 1);

        const uint32_t a0 = ld_c32_el(cw + w0, pol);
        const uint32_t b0v = ld_c32_el(cw + w0 + 1, pol);
        const uint32_t a1 = ld_c32_el(cw + w1, pol);
        const uint32_t b1v = ld_c32_el(cw + w1 + 1, pol);

        const __half2 ha0 = *(const __half2*)&a0, hb0 = *(const __half2*)&b0v;
        const __half2 ha1 = *(const __half2*)&a1, hb1 = *(const __half2*)&b1v;

        const float sm0 = __half2float(o0 ? __high2half(ha0) : __low2half(ha0));
        const float sd0 = __half2float(o0 ? __low2half(hb0) : __high2half(ha0));
        const float sp0 = __half2float(o0 ? __high2half(hb0) : __low2half(hb0));
        const float sm1 = __half2float(o1 ? __high2half(ha1) : __low2half(ha1));
        const float sd1 = __half2float(o1 ? __low2half(hb1) : __high2half(ha1));
        const float sp1 = __half2float(o1 ? __high2half(hb1) : __low2half(hb1));

        const float gs0 = s_gs[d0];
        const float cs0 = s_cs[s0];
        const float gs1 = s_gs[d1];
        const float cs1 = s_cs[s1];

        {
            const float mu_ = 1.0f / (1.0f + __expf(-(sm0 + bmv)));
            const float piv = 1.0f / (1.0f + __expf(-(sp0 + bpv)));
            const float x = gs0 * (sd0 + bdv);
            const float spv = fmaxf(x, 0.0f) + log1pf(__expf(-fabsf(x)));
            const float dispv = fminf(fmaxf(spv, 1e-4f), 1e4f);
            const float muv = cs0 * fminf(fmaxf(__expf(gs0 * mu_) - 1.0f, 1e-5f), 1e6f);
            __stcs(out + e0, muv);
            __stcs(out + e0 + E, dispv);
            __stcs(out + e0 + 2 * (size_t)E, piv);
        }
        if (v1) {
            const float mu_ = 1.0f / (1.0f + __expf(-(sm1 + bmv)));
            const float piv = 1.0f / (1.0f + __expf(-(sp1 + bpv)));
            const float x = gs1 * (sd1 + bdv);
            const float spv = fmaxf(x, 0.0f) + log1pf(__expf(-fabsf(x)));
            const float dispv = fminf(fmaxf(spv, 1e-4f), 1e4f);
            const float muv = cs1 * fminf(fmaxf(__expf(gs1 * mu_) - 1.0f, 1e-5f), 1e6f);
            __stcs(out + e1, muv);
            __stcs(out + e1 + E, dispv);
            __stcs(out + e1 + 2 * (size_t)E, piv);
        }
    }
}

// ---------------- launch -----------------------------------------------------
extern "C" void kernel_launch(void* const* d_in, const int* in_sizes, int n_in,
                              void* d_out, int out_size) {
    const float* c_feat    = (const float*)d_in[0];
    const float* g_feat    = (const float*)d_in[1];
    const float* cs_factor = (const float*)d_in[2];
    const float* gs_factor = (const float*)d_in[3];
    const int*   src       = (const int*)d_in[4];
    const int*   dst       = (const int*)d_in[5];
    const float* Wm        = (const float*)d_in[6];
    const float* bm        = (const float*)d_in[7];
    const float* Wd        = (const float*)d_in[8];
    const float* bd        = (const float*)d_in[9];
    const float* Wp        = (const float*)d_in[10];
    const float* bp        = (const float*)d_in[11];
    float* out = (float*)d_out;
    const int E = in_sizes[4];

    const int nPrep = (M_PAD + N_PAD) * DD;
    prep_AB<<<(nPrep + 255) / 256, 256>>>(c_feat, g_feat, Wm, Wd, Wp);

    const int dyn_bytes = 3 * 128 * SA;   // 55296
    cudaFuncSetAttribute(zinb_gemm, cudaFuncAttributeMaxDynamicSharedMemorySize,
                         dyn_bytes);
    dim3 grid(NTT, NGRP);
    zinb_gemm<<<grid, 256, dyn_bytes>>>();

    // Persistent-ish grid: amortize the 48KB smem factor fill per block.
    zinb_gather<<<592, 256>>>(src, dst, cs_factor, gs_factor,
                              bm, bd, bp, out, E);
}